// round 12
// baseline (speedup 1.0000x reference)
#include <cuda_runtime.h>
#include <cuda_fp16.h>
#include <stdint.h>

typedef __half f16;

#define S_LEN 512
#define BATCH 128
#define IDIM  1024
#define HDIM  1024
#define KDIM  2048       // packed weights: k<1024 -> Wih, k>=1024 -> Whh
#define N3    3072       // 3 gates * H, interleaved col = 3*j + gate
#define MTOT  (S_LEN*BATCH)

#define TN_S  48               // step N tile (2 ngrp x 24)
#define TN_G  96               // gi N tile   (2 ngrp x 48)
#define NBLK_S (N3/TN_S)       // 64
#define NBLK_G (N3/TN_G)       // 32

// ---- gi GEMM layout (KT=32/ASTR=40) ----
#define KT    32
#define ASTR  40
#define NSTG  3
#define STAGE_G ((128 + TN_G)*ASTR)        // 8960 f16
#define SMEM_G  (NSTG*STAGE_G*2)           // 53760 B

// ---- persistent kernel layout (KT=64 / ASTR=72, pair-private A) ----
#define KTP    64
#define ASTRP  72
#define NKTP   (HDIM/KTP)                  // 16
#define APAIR  (16*ASTRP)                  // 1152 f16 per pair stage
#define APBLK  (NSTG*APAIR)                // 3456 f16 per pair
#define W_OFF  (8*APBLK)                   // 27648 f16
#define W_CH   (TN_S*ASTRP)                // 3456 f16 per k-chunk
#define SMEM_P ((W_OFF + NKTP*W_CH)*2)     // 165888 B

// ---------------- device scratch ----------------
__device__ f16   g_x[(size_t)MTOT*IDIM];
__device__ f16   g_W[(size_t)2*N3*KDIM];     // [dir][n][k] fp16
__device__ float g_bias[2][4][HDIM];         // br, bz, b_in, b_hn
__device__ f16   g_hf[2*2*BATCH*HDIM];       // [parity][dir][b][j]
__device__ float g_gi[(size_t)2*MTOT*N3];    // precomputed x@Wih^T
__device__ unsigned g_flags[2][64];          // per-CTA monotone step counters

// ---------------- helpers ----------------
__device__ __forceinline__ void cp16(f16* dst, const f16* src) {
    unsigned d = (unsigned)__cvta_generic_to_shared(dst);
    asm volatile("cp.async.cg.shared.global [%0], [%1], 16;\n" :: "r"(d), "l"(src));
}
__device__ __forceinline__ uint32_t smaddr(const void* p) {
    return (uint32_t)__cvta_generic_to_shared(p);
}
__device__ __forceinline__ void ldsm_x4(uint32_t r[4], uint32_t a) {
    asm volatile("ldmatrix.sync.aligned.m8n8.x4.shared.b16 {%0,%1,%2,%3},[%4];"
                 : "=r"(r[0]), "=r"(r[1]), "=r"(r[2]), "=r"(r[3]) : "r"(a));
}
__device__ __forceinline__ void mma16816(float c[4], const uint32_t a[4],
                                         uint32_t b0, uint32_t b1) {
    asm volatile(
        "mma.sync.aligned.m16n8k16.row.col.f32.f16.f16.f32 "
        "{%0,%1,%2,%3},{%4,%5,%6,%7},{%8,%9},{%0,%1,%2,%3};"
        : "+f"(c[0]), "+f"(c[1]), "+f"(c[2]), "+f"(c[3])
        : "r"(a[0]), "r"(a[1]), "r"(a[2]), "r"(a[3]), "r"(b0), "r"(b1));
}
__device__ __forceinline__ float fsig(float x) {
    return __fdividef(1.f, 1.f + __expf(-x));
}
__device__ __forceinline__ float ftanh(float x) {
    return 1.f - __fdividef(2.f, __expf(2.f * x) + 1.f);
}
__device__ __forceinline__ void bar_pair(int id) {
    asm volatile("bar.sync %0, 64;" :: "r"(id) : "memory");
}

#define CP_COMMIT() asm volatile("cp.async.commit_group;")

// ---------------- prep kernels ----------------
__global__ void pack_x_kernel(const float* __restrict__ x) {
    int i = blockIdx.x * 256 + threadIdx.x;
    g_x[i] = __float2half_rn(x[i]);
}

__global__ void pack_w_kernel(const float* __restrict__ Wih_f, const float* __restrict__ Whh_f,
                              const float* __restrict__ Wih_b, const float* __restrict__ Whh_b) {
    int idx = blockIdx.x * 256 + threadIdx.x;
    int k   = idx % KDIM;
    int n   = (idx / KDIM) % N3;
    int dir = idx / (KDIM * N3);
    int j = n / 3, g = n % 3;
    int srow = g * HDIM + j;
    const float* Wih = dir ? Wih_b : Wih_f;
    const float* Whh = dir ? Whh_b : Whh_f;
    float v = (k < IDIM) ? Wih[srow * IDIM + k] : Whh[srow * HDIM + (k - IDIM)];
    g_W[idx] = __float2half_rn(v);
}

__global__ void pack_bias_kernel(const float* __restrict__ bih_f, const float* __restrict__ bhh_f,
                                 const float* __restrict__ bih_b, const float* __restrict__ bhh_b) {
    int i = blockIdx.x * 256 + threadIdx.x;   // 0..2047
    int dir = i >> 10, j = i & 1023;
    const float* bih = dir ? bih_b : bih_f;
    const float* bhh = dir ? bhh_b : bhh_f;
    g_bias[dir][0][j] = bih[j] + bhh[j];
    g_bias[dir][1][j] = bih[HDIM + j] + bhh[HDIM + j];
    g_bias[dir][2][j] = bih[2 * HDIM + j];
    g_bias[dir][3][j] = bhh[2 * HDIM + j];
}

__global__ void init_h_kernel() {
    int i = blockIdx.x * 256 + threadIdx.x;   // 2*2*B*H
    g_hf[i] = __float2half_rn(0.f);
    if (i < 128) ((unsigned*)g_flags)[i] = 0u;
}

// ---------------- warp compute over 32 k (generic, used by gi_gemm) ----------------
template<int NT, int AST>
__device__ __forceinline__ void compute_tile(f16* pA, f16* pB, int mwarp, int ngrp,
                                             int lane, float acc[NT][4]) {
    const uint32_t aoff = smaddr(pA + (mwarp * 16 + (lane & 15)) * AST + (lane >> 4) * 8);
    const uint32_t boff = smaddr(pB + (ngrp * (NT * 8) + (lane & 7)) * AST + (lane >> 3) * 8);
    uint32_t a0[4], a1[4];
    ldsm_x4(a0, aoff);
    ldsm_x4(a1, aoff + 16 * 2);
#pragma unroll
    for (int nt = 0; nt < NT; ++nt) {
        uint32_t b4[4];
        ldsm_x4(b4, boff + nt * 8 * AST * 2);
        mma16816(acc[nt], a0, b4[0], b4[1]);
        mma16816(acc[nt], a1, b4[2], b4[3]);
    }
}

// pair-local variant: A buffer holds only this pair's 16 rows
template<int NT>
__device__ __forceinline__ void compute_pair(f16* pA, f16* pW, int ngrp,
                                             int lane, float acc[NT][4]) {
    const uint32_t aoff = smaddr(pA + (lane & 15) * ASTRP + (lane >> 4) * 8);
    const uint32_t boff = smaddr(pW + (ngrp * (NT * 8) + (lane & 7)) * ASTRP + (lane >> 3) * 8);
    uint32_t a0[4], a1[4];
    ldsm_x4(a0, aoff);
    ldsm_x4(a1, aoff + 16 * 2);
#pragma unroll
    for (int nt = 0; nt < NT; ++nt) {
        uint32_t b4[4];
        ldsm_x4(b4, boff + nt * 8 * ASTRP * 2);
        mma16816(acc[nt], a0, b4[0], b4[1]);
        mma16816(acc[nt], a1, b4[2], b4[3]);
    }
}

// ---------------- pre-GEMM: gi = x @ Wih^T (unchanged) ----------------
// grid: (NBLK_G=32, MTOT/128=512, 2), block 512 (16 warps: 8 M x 2 N)
__global__ void __launch_bounds__(512) gi_gemm() {
    extern __shared__ char smraw[];
    f16* sm = (f16*)smraw;

    const int nblk = blockIdx.x, mblk = blockIdx.y, dir = blockIdx.z;
    const int t = threadIdx.x, warp = t >> 5, lane = t & 31;
    const int mwarp = warp & 7, ngrp = warp >> 3;
    const int grp = lane >> 2, tq = lane & 3;

    auto stage = [&](int s) { return sm + s * STAGE_G; };

    auto copy_tile = [&](int kt, int buf) {
        f16* st = stage(buf);
        const int k0 = kt * KT;
        {
            int row = t >> 2;
            int kq  = (t & 3) * 8;
            size_t off = ((size_t)mblk * 128 + row) * IDIM + k0 + kq;
            cp16(st + row * ASTR + kq, g_x + off);
        }
        if (t < 4 * TN_G) {
            int nloc = t >> 2;
            int kq   = (t & 3) * 8;
            size_t off = ((size_t)(dir * N3 + nblk * TN_G + nloc)) * KDIM + k0 + kq;
            cp16(st + 128 * ASTR + nloc * ASTR + kq, g_W + off);
        }
    };

    float acc[6][4];
#pragma unroll
    for (int i = 0; i < 6; i++)
#pragma unroll
        for (int q = 0; q < 4; q++) acc[i][q] = 0.f;

    copy_tile(0, 0); CP_COMMIT();
    copy_tile(1, 1); CP_COMMIT();

    const int NKT = IDIM / KT;   // 32
#pragma unroll 1
    for (int kt = 0; kt < NKT; ++kt) {
        if (kt < NKT - 1) asm volatile("cp.async.wait_group 1;");
        else              asm volatile("cp.async.wait_group 0;");
        __syncthreads();
        if (kt + 2 < NKT) { copy_tile(kt + 2, (kt + 2) % NSTG); CP_COMMIT(); }
        compute_tile<6, ASTR>(stage(kt % NSTG), stage(kt % NSTG) + 128 * ASTR,
                              mwarp, ngrp, lane, acc);
    }

    const int m = mblk * 128 + mwarp * 16 + grp;
    const int colbase = nblk * TN_G + ngrp * 48 + tq * 2;
    float* d0 = g_gi + ((size_t)dir * MTOT + m) * N3;
    float* d1 = d0 + (size_t)8 * N3;
#pragma unroll
    for (int nt = 0; nt < 6; ++nt) {
        int col = colbase + nt * 8;
        d0[col]     = acc[nt][0];
        d0[col + 1] = acc[nt][1];
        d1[col]     = acc[nt][2];
        d1[col + 1] = acc[nt][3];
    }
}

// ---------------- persistent recurrent kernel ----------------
// grid: (NBLK_S=64, 2) = 128 CTAs, block 512 (8 warp-pairs).
// Per-CTA monotone flags + per-chunk dependency polling: no global barrier.
__global__ void __launch_bounds__(512) gru_persist(float* __restrict__ out) {
    extern __shared__ char smraw[];
    f16* sm  = (f16*)smraw;
    f16* wsm = sm + W_OFF;

    const int nblk = blockIdx.x, dir = blockIdx.y;
    const int t = threadIdx.x, warp = t >> 5, lane = t & 31;
    const int mwarp = warp & 7, ngrp = warp >> 3;
    const int grp = lane >> 2, tq = lane & 3;
    const int u = lane + (ngrp << 5);            // pair-local thread id 0..63
    const int barid = mwarp + 1;                 // named barrier per pair
    f16* apair = sm + mwarp * APBLK;

    // ---- preload Whh tile: 16 chunks x 48 rows x 64 k ----
    for (int i = t; i < NKTP * TN_S * 8; i += 512) {
        int kt   = i / (TN_S * 8);
        int r    = i % (TN_S * 8);
        int nloc = r >> 3, kq = (r & 7) * 8;
        size_t off = ((size_t)(dir * N3 + nblk * TN_S + nloc)) * KDIM + IDIM + kt * KTP + kq;
        cp16(wsm + kt * W_CH + nloc * ASTRP + kq, g_W + off);
    }
    CP_COMMIT();
    asm volatile("cp.async.wait_group 0;");
    __syncthreads();

    // ---- per-thread persistent state: one b, 4 consecutive j ----
    const int brow = mwarp * 16 + (u >> 2);          // batch row
    const int jb   = nblk * 16 + (u & 3) * 4;        // first j of 4
    const int c0   = (u & 3) * 12;                   // first col in pair's 48-col tile
    float hreg[4];
    float bs0[4], bs1[4], bs2[4], bs3[4];
#pragma unroll
    for (int q = 0; q < 4; q++) {
        hreg[q] = 0.f;
        bs0[q] = g_bias[dir][0][jb + q];
        bs1[q] = g_bias[dir][1][jb + q];
        bs2[q] = g_bias[dir][2][jb + q];
        bs3[q] = g_bias[dir][3][jb + q];
    }

    volatile unsigned* flg = g_flags[dir];

#pragma unroll 1
    for (int step = 0; step < S_LEN; ++step) {
        const int rpar = step & 1, wpar = rpar ^ 1;
        const int s_x  = dir ? (S_LEN - 1 - step) : step;
        const int hbase = (rpar * 2 + dir) * BATCH * HDIM;
        const unsigned target = (unsigned)step;      // need producers done with step-1

        // poll the 4 producer CTAs of chunk kt (u<4 threads of the pair)
        auto poll4 = [&](int kt) {
            if (u < 4) {
                while (flg[4 * kt + u] < target) __nanosleep(32);
                __threadfence();
            }
        };

        auto copyA = [&](int kt, int buf) {
            f16* st = apair + buf * APAIR;
#pragma unroll
            for (int i = 0; i < 2; i++) {
                int slot = u + 64 * i;               // 128 slots: 16 rows x 8 kq
                int rl = slot >> 3, kq = (slot & 7) * 8;
                int off = hbase + (mwarp * 16 + rl) * HDIM + kt * KTP + kq;
                cp16(st + rl * ASTRP + kq, g_hf + off);
            }
        };

        float acc[3][4];
#pragma unroll
        for (int i = 0; i < 3; i++)
#pragma unroll
            for (int q = 0; q < 4; q++) acc[i][q] = 0.f;

        // prologue: gate chunks 0,1 on their producers, then issue
        poll4(0);
        poll4(1);
        bar_pair(barid);
        copyA(0, 0); CP_COMMIT();
        copyA(1, 1); CP_COMMIT();

        // ---- prefetch gi (12 consecutive floats) — hidden behind mainloop ----
        const float* gp = g_gi + ((size_t)dir * MTOT + (size_t)s_x * BATCH + brow) * N3
                          + nblk * TN_S + c0;
        float4 giA = __ldg((const float4*)gp);
        float4 giB = __ldg((const float4*)(gp + 4));
        float4 giC = __ldg((const float4*)(gp + 8));
        float giv[12] = {giA.x, giA.y, giA.z, giA.w, giB.x, giB.y, giB.z, giB.w,
                         giC.x, giC.y, giC.z, giC.w};

#pragma unroll 1
        for (int kt = 0; kt < NKTP; ++kt) {
            if (kt + 2 < NKTP) poll4(kt + 2);        // gate the chunk we're about to issue
            if (kt < NKTP - 1) asm volatile("cp.async.wait_group 1;");
            else               asm volatile("cp.async.wait_group 0;");
            bar_pair(barid);
            if (kt + 2 < NKTP) { copyA(kt + 2, (kt + 2) % NSTG); CP_COMMIT(); }
            f16* pA = apair + (kt % NSTG) * APAIR;
            f16* pW = wsm + kt * W_CH;
            compute_pair<3>(pA, pW, ngrp, lane, acc);
            compute_pair<3>(pA + 32, pW + 32, ngrp, lane, acc);
        }

        // ---- pair-local epilogue: frags -> pair smem -> gates ----
        bar_pair(barid);                              // A region reads done
        float* sCp = (float*)apair;                   // 16 x 49 floats (3136 B)
        {
            const int colb = ngrp * 24 + tq * 2;
#pragma unroll
            for (int nt = 0; nt < 3; ++nt) {
                int col = colb + nt * 8;
                sCp[grp * 49 + col]           = acc[nt][0];
                sCp[grp * 49 + col + 1]       = acc[nt][1];
                sCp[(grp + 8) * 49 + col]     = acc[nt][2];
                sCp[(grp + 8) * 49 + col + 1] = acc[nt][3];
            }
        }
        bar_pair(barid);

        const float* sRow = sCp + (u >> 2) * 49 + c0;
#pragma unroll
        for (int q = 0; q < 4; q++) {
            float gr  = sRow[q * 3]     + giv[q * 3]     + bs0[q];
            float gz  = sRow[q * 3 + 1] + giv[q * 3 + 1] + bs1[q];
            float gnh = sRow[q * 3 + 2] + bs3[q];
            float gni = giv[q * 3 + 2] + bs2[q];
            float r = fsig(gr);
            float z = fsig(gz);
            float n = ftanh(gni + r * gnh);
            hreg[q] = (1.f - z) * n + z * hreg[q];
        }
        // packed h store (4 consecutive f16 = 8 B)
        {
            __half2 lo2 = __halves2half2(__float2half_rn(hreg[0]), __float2half_rn(hreg[1]));
            __half2 hi2 = __halves2half2(__float2half_rn(hreg[2]), __float2half_rn(hreg[3]));
            uint2 v;
            v.x = *(const unsigned*)&lo2;
            v.y = *(const unsigned*)&hi2;
            *(uint2*)(g_hf + ((wpar * 2 + dir) * BATCH + brow) * HDIM + jb) = v;
        }

        // publish completion: all h stores visible, then set this CTA's flag
        __threadfence();
        __syncthreads();
        if (t == 0) flg[nblk] = (unsigned)(step + 1);

        // out store (float4) — off the critical path
        {
            float4 o = make_float4(hreg[0], hreg[1], hreg[2], hreg[3]);
            *(float4*)(out + ((size_t)step * BATCH + brow) * (2 * HDIM) + dir * HDIM + jb) = o;
        }
    }
}

// ---------------- launch ----------------
extern "C" void kernel_launch(void* const* d_in, const int* in_sizes, int n_in,
                              void* d_out, int out_size) {
    const float* x     = (const float*)d_in[0];
    const float* Wih_f = (const float*)d_in[1];
    const float* Whh_f = (const float*)d_in[2];
    const float* bih_f = (const float*)d_in[3];
    const float* bhh_f = (const float*)d_in[4];
    const float* Wih_b = (const float*)d_in[5];
    const float* Whh_b = (const float*)d_in[6];
    const float* bih_b = (const float*)d_in[7];
    const float* bhh_b = (const float*)d_in[8];
    float* out = (float*)d_out;

    cudaFuncSetAttribute(gi_gemm,     cudaFuncAttributeMaxDynamicSharedMemorySize, SMEM_G);
    cudaFuncSetAttribute(gru_persist, cudaFuncAttributeMaxDynamicSharedMemorySize, SMEM_P);

    pack_x_kernel<<<(int)((size_t)MTOT * IDIM / 256), 256>>>(x);
    pack_w_kernel<<<2 * N3 * KDIM / 256, 256>>>(Wih_f, Whh_f, Wih_b, Whh_b);
    pack_bias_kernel<<<8, 256>>>(bih_f, bhh_f, bih_b, bhh_b);
    init_h_kernel<<<2 * 2 * BATCH * HDIM / 256, 256>>>();

    gi_gemm<<<dim3(NBLK_G, MTOT / 128, 2), 512, SMEM_G>>>();

    gru_persist<<<dim3(NBLK_S, 2), 512, SMEM_P>>>(out);
}

// round 13
// speedup vs baseline: 1.8046x; 1.8046x over previous
#include <cuda_runtime.h>
#include <cuda_fp16.h>
#include <stdint.h>

typedef __half f16;

#define S_LEN 512
#define BATCH 128
#define IDIM  1024
#define HDIM  1024
#define KDIM  2048       // packed weights: k<1024 -> Wih, k>=1024 -> Whh
#define N3    3072       // 3 gates * H, interleaved col = 3*j + gate
#define MTOT  (S_LEN*BATCH)

#define TN_S  48               // step N tile (2 ngrp x 24)
#define TN_G  96               // gi N tile   (2 ngrp x 48)
#define NBLK_S (N3/TN_S)       // 64
#define NBLK_G (N3/TN_G)       // 32

// ---- gi GEMM layout (KT=32/ASTR=40) ----
#define KT    32
#define ASTR  40
#define NSTG  3
#define STAGE_G ((128 + TN_G)*ASTR)        // 8960 f16
#define SMEM_G  (NSTG*STAGE_G*2)           // 53760 B

// ---- persistent kernel layout (KT=64 / ASTR=72, pair-private A) ----
#define KTP    64
#define ASTRP  72
#define NKTP   (HDIM/KTP)                  // 16
#define APAIR  (16*ASTRP)                  // 1152 f16 per pair stage
#define APBLK  (NSTG*APAIR)                // 3456 f16 per pair
#define W_OFF  (8*APBLK)                   // 27648 f16
#define W_CH   (TN_S*ASTRP)                // 3456 f16 per k-chunk
#define SC_OFF (W_OFF + NKTP*W_CH)         // 82944 f16 — start of epilogue buffers
#define SC_PAIR (16*49)                    // 784 floats per pair
#define SMEM_P (SC_OFF*2 + 8*SC_PAIR*4)    // 165888 + 25088 = 190976 B

// ---------------- device scratch ----------------
__device__ f16   g_x[(size_t)MTOT*IDIM];
__device__ f16   g_W[(size_t)2*N3*KDIM];     // [dir][n][k] fp16
__device__ float g_bias[2][4][HDIM];         // br, bz, b_in, b_hn
__device__ f16   g_hf[2*2*BATCH*HDIM];       // [parity][dir][b][j]
__device__ float g_gi[(size_t)2*MTOT*N3];    // precomputed x@Wih^T
__device__ unsigned g_bar2[2];               // per-dir barrier counters

// ---------------- helpers ----------------
__device__ __forceinline__ void cp16(f16* dst, const f16* src) {
    unsigned d = (unsigned)__cvta_generic_to_shared(dst);
    asm volatile("cp.async.cg.shared.global [%0], [%1], 16;\n" :: "r"(d), "l"(src));
}
__device__ __forceinline__ uint32_t smaddr(const void* p) {
    return (uint32_t)__cvta_generic_to_shared(p);
}
__device__ __forceinline__ void ldsm_x4(uint32_t r[4], uint32_t a) {
    asm volatile("ldmatrix.sync.aligned.m8n8.x4.shared.b16 {%0,%1,%2,%3},[%4];"
                 : "=r"(r[0]), "=r"(r[1]), "=r"(r[2]), "=r"(r[3]) : "r"(a));
}
__device__ __forceinline__ void mma16816(float c[4], const uint32_t a[4],
                                         uint32_t b0, uint32_t b1) {
    asm volatile(
        "mma.sync.aligned.m16n8k16.row.col.f32.f16.f16.f32 "
        "{%0,%1,%2,%3},{%4,%5,%6,%7},{%8,%9},{%0,%1,%2,%3};"
        : "+f"(c[0]), "+f"(c[1]), "+f"(c[2]), "+f"(c[3])
        : "r"(a[0]), "r"(a[1]), "r"(a[2]), "r"(a[3]), "r"(b0), "r"(b1));
}
__device__ __forceinline__ float fsig(float x) {
    return __fdividef(1.f, 1.f + __expf(-x));
}
__device__ __forceinline__ float ftanh(float x) {
    return 1.f - __fdividef(2.f, __expf(2.f * x) + 1.f);
}
__device__ __forceinline__ void bar_pair(int id) {
    asm volatile("bar.sync %0, 64;" :: "r"(id) : "memory");
}

#define CP_COMMIT() asm volatile("cp.async.commit_group;")

// ---------------- prep kernels ----------------
__global__ void pack_x_kernel(const float* __restrict__ x) {
    int i = blockIdx.x * 256 + threadIdx.x;
    g_x[i] = __float2half_rn(x[i]);
}

__global__ void pack_w_kernel(const float* __restrict__ Wih_f, const float* __restrict__ Whh_f,
                              const float* __restrict__ Wih_b, const float* __restrict__ Whh_b) {
    int idx = blockIdx.x * 256 + threadIdx.x;
    int k   = idx % KDIM;
    int n   = (idx / KDIM) % N3;
    int dir = idx / (KDIM * N3);
    int j = n / 3, g = n % 3;
    int srow = g * HDIM + j;
    const float* Wih = dir ? Wih_b : Wih_f;
    const float* Whh = dir ? Whh_b : Whh_f;
    float v = (k < IDIM) ? Wih[srow * IDIM + k] : Whh[srow * HDIM + (k - IDIM)];
    g_W[idx] = __float2half_rn(v);
}

__global__ void pack_bias_kernel(const float* __restrict__ bih_f, const float* __restrict__ bhh_f,
                                 const float* __restrict__ bih_b, const float* __restrict__ bhh_b) {
    int i = blockIdx.x * 256 + threadIdx.x;   // 0..2047
    int dir = i >> 10, j = i & 1023;
    const float* bih = dir ? bih_b : bih_f;
    const float* bhh = dir ? bhh_b : bhh_f;
    g_bias[dir][0][j] = bih[j] + bhh[j];
    g_bias[dir][1][j] = bih[HDIM + j] + bhh[HDIM + j];
    g_bias[dir][2][j] = bih[2 * HDIM + j];
    g_bias[dir][3][j] = bhh[2 * HDIM + j];
}

__global__ void init_h_kernel() {
    int i = blockIdx.x * 256 + threadIdx.x;   // 2*2*B*H
    g_hf[i] = __float2half_rn(0.f);
    if (i < 2) g_bar2[i] = 0u;
}

// ---------------- warp compute over 32 k (generic, used by gi_gemm) ----------------
template<int NT, int AST>
__device__ __forceinline__ void compute_tile(f16* pA, f16* pB, int mwarp, int ngrp,
                                             int lane, float acc[NT][4]) {
    const uint32_t aoff = smaddr(pA + (mwarp * 16 + (lane & 15)) * AST + (lane >> 4) * 8);
    const uint32_t boff = smaddr(pB + (ngrp * (NT * 8) + (lane & 7)) * AST + (lane >> 3) * 8);
    uint32_t a0[4], a1[4];
    ldsm_x4(a0, aoff);
    ldsm_x4(a1, aoff + 16 * 2);
#pragma unroll
    for (int nt = 0; nt < NT; ++nt) {
        uint32_t b4[4];
        ldsm_x4(b4, boff + nt * 8 * AST * 2);
        mma16816(acc[nt], a0, b4[0], b4[1]);
        mma16816(acc[nt], a1, b4[2], b4[3]);
    }
}

// pair-local variant: A buffer holds only this pair's 16 rows
template<int NT>
__device__ __forceinline__ void compute_pair(f16* pA, f16* pW, int ngrp,
                                             int lane, float acc[NT][4]) {
    const uint32_t aoff = smaddr(pA + (lane & 15) * ASTRP + (lane >> 4) * 8);
    const uint32_t boff = smaddr(pW + (ngrp * (NT * 8) + (lane & 7)) * ASTRP + (lane >> 3) * 8);
    uint32_t a0[4], a1[4];
    ldsm_x4(a0, aoff);
    ldsm_x4(a1, aoff + 16 * 2);
#pragma unroll
    for (int nt = 0; nt < NT; ++nt) {
        uint32_t b4[4];
        ldsm_x4(b4, boff + nt * 8 * ASTRP * 2);
        mma16816(acc[nt], a0, b4[0], b4[1]);
        mma16816(acc[nt], a1, b4[2], b4[3]);
    }
}

// ---------------- pre-GEMM: gi = x @ Wih^T ----------------
// grid: (NBLK_G=32, MTOT/128=512, 2), block 512 (16 warps: 8 M x 2 N)
__global__ void __launch_bounds__(512) gi_gemm() {
    extern __shared__ char smraw[];
    f16* sm = (f16*)smraw;

    const int nblk = blockIdx.x, mblk = blockIdx.y, dir = blockIdx.z;
    const int t = threadIdx.x, warp = t >> 5, lane = t & 31;
    const int mwarp = warp & 7, ngrp = warp >> 3;
    const int grp = lane >> 2, tq = lane & 3;

    auto stage = [&](int s) { return sm + s * STAGE_G; };

    auto copy_tile = [&](int kt, int buf) {
        f16* st = stage(buf);
        const int k0 = kt * KT;
        {
            int row = t >> 2;
            int kq  = (t & 3) * 8;
            size_t off = ((size_t)mblk * 128 + row) * IDIM + k0 + kq;
            cp16(st + row * ASTR + kq, g_x + off);
        }
        if (t < 4 * TN_G) {
            int nloc = t >> 2;
            int kq   = (t & 3) * 8;
            size_t off = ((size_t)(dir * N3 + nblk * TN_G + nloc)) * KDIM + k0 + kq;
            cp16(st + 128 * ASTR + nloc * ASTR + kq, g_W + off);
        }
    };

    float acc[6][4];
#pragma unroll
    for (int i = 0; i < 6; i++)
#pragma unroll
        for (int q = 0; q < 4; q++) acc[i][q] = 0.f;

    copy_tile(0, 0); CP_COMMIT();
    copy_tile(1, 1); CP_COMMIT();

    const int NKT = IDIM / KT;   // 32
#pragma unroll 1
    for (int kt = 0; kt < NKT; ++kt) {
        if (kt < NKT - 1) asm volatile("cp.async.wait_group 1;");
        else              asm volatile("cp.async.wait_group 0;");
        __syncthreads();
        if (kt + 2 < NKT) { copy_tile(kt + 2, (kt + 2) % NSTG); CP_COMMIT(); }
        compute_tile<6, ASTR>(stage(kt % NSTG), stage(kt % NSTG) + 128 * ASTR,
                              mwarp, ngrp, lane, acc);
    }

    const int m = mblk * 128 + mwarp * 16 + grp;
    const int colbase = nblk * TN_G + ngrp * 48 + tq * 2;
    float* d0 = g_gi + ((size_t)dir * MTOT + m) * N3;
    float* d1 = d0 + (size_t)8 * N3;
#pragma unroll
    for (int nt = 0; nt < 6; ++nt) {
        int col = colbase + nt * 8;
        d0[col]     = acc[nt][0];
        d0[col + 1] = acc[nt][1];
        d1[col]     = acc[nt][2];
        d1[col + 1] = acc[nt][3];
    }
}

// ---------------- persistent recurrent kernel ----------------
// grid: (NBLK_S=64, 2) = 128 CTAs, block 512 (8 warp-pairs).
// Pair-private A staging + named pair barriers; per-dir global barrier per step.
// Epilogue fragments go to a dedicated smem region (one pair-barrier only).
__global__ void __launch_bounds__(512) gru_persist(float* __restrict__ out) {
    extern __shared__ char smraw[];
    f16* sm  = (f16*)smraw;
    f16* wsm = sm + W_OFF;

    const int nblk = blockIdx.x, dir = blockIdx.y;
    const int t = threadIdx.x, warp = t >> 5, lane = t & 31;
    const int mwarp = warp & 7, ngrp = warp >> 3;
    const int grp = lane >> 2, tq = lane & 3;
    const int u = lane + (ngrp << 5);            // pair-local thread id 0..63
    const int barid = mwarp + 1;                 // named barrier per pair
    f16* apair = sm + mwarp * APBLK;
    float* sCp = (float*)(smraw + SC_OFF * 2) + mwarp * SC_PAIR;   // 16 x 49 floats

    // ---- preload Whh tile: 16 chunks x 48 rows x 64 k ----
    for (int i = t; i < NKTP * TN_S * 8; i += 512) {
        int kt   = i / (TN_S * 8);
        int r    = i % (TN_S * 8);
        int nloc = r >> 3, kq = (r & 7) * 8;
        size_t off = ((size_t)(dir * N3 + nblk * TN_S + nloc)) * KDIM + IDIM + kt * KTP + kq;
        cp16(wsm + kt * W_CH + nloc * ASTRP + kq, g_W + off);
    }
    CP_COMMIT();
    asm volatile("cp.async.wait_group 0;");
    __syncthreads();

    // ---- per-thread persistent state: one b, 4 consecutive j ----
    const int brow = mwarp * 16 + (u >> 2);          // batch row
    const int jb   = nblk * 16 + (u & 3) * 4;        // first j of 4
    const int c0   = (u & 3) * 12;                   // first col in pair's 48-col tile
    float hreg[4];
    float bs0[4], bs1[4], bs2[4], bs3[4];
#pragma unroll
    for (int q = 0; q < 4; q++) {
        hreg[q] = 0.f;
        bs0[q] = g_bias[dir][0][jb + q];
        bs1[q] = g_bias[dir][1][jb + q];
        bs2[q] = g_bias[dir][2][jb + q];
        bs3[q] = g_bias[dir][3][jb + q];
    }

#pragma unroll 1
    for (int step = 0; step < S_LEN; ++step) {
        const int rpar = step & 1, wpar = rpar ^ 1;
        const int s_x  = dir ? (S_LEN - 1 - step) : step;
        const int hbase = (rpar * 2 + dir) * BATCH * HDIM;

        auto copyA = [&](int kt, int buf) {
            f16* st = apair + buf * APAIR;
#pragma unroll
            for (int i = 0; i < 2; i++) {
                int slot = u + 64 * i;               // 128 slots: 16 rows x 8 kq
                int rl = slot >> 3, kq = (slot & 7) * 8;
                int off = hbase + (mwarp * 16 + rl) * HDIM + kt * KTP + kq;
                cp16(st + rl * ASTRP + kq, g_hf + off);
            }
        };

        float acc[3][4];
#pragma unroll
        for (int i = 0; i < 3; i++)
#pragma unroll
            for (int q = 0; q < 4; q++) acc[i][q] = 0.f;

        copyA(0, 0); CP_COMMIT();
        copyA(1, 1); CP_COMMIT();

        // ---- prefetch gi (12 consecutive floats) — hidden behind mainloop ----
        const float* gp = g_gi + ((size_t)dir * MTOT + (size_t)s_x * BATCH + brow) * N3
                          + nblk * TN_S + c0;
        float4 giA = __ldg((const float4*)gp);
        float4 giB = __ldg((const float4*)(gp + 4));
        float4 giC = __ldg((const float4*)(gp + 8));
        float giv[12] = {giA.x, giA.y, giA.z, giA.w, giB.x, giB.y, giB.z, giB.w,
                         giC.x, giC.y, giC.z, giC.w};

#pragma unroll 1
        for (int kt = 0; kt < NKTP; ++kt) {
            if (kt < NKTP - 1) asm volatile("cp.async.wait_group 1;");
            else               asm volatile("cp.async.wait_group 0;");
            bar_pair(barid);
            if (kt + 2 < NKTP) { copyA(kt + 2, (kt + 2) % NSTG); CP_COMMIT(); }
            f16* pA = apair + (kt % NSTG) * APAIR;
            f16* pW = wsm + kt * W_CH;
            compute_pair<3>(pA, pW, ngrp, lane, acc);
            compute_pair<3>(pA + 32, pW + 32, ngrp, lane, acc);
        }

        // ---- pair-local epilogue: frags -> dedicated pair smem -> gates ----
        {
            const int colb = ngrp * 24 + tq * 2;
#pragma unroll
            for (int nt = 0; nt < 3; ++nt) {
                int col = colb + nt * 8;
                sCp[grp * 49 + col]           = acc[nt][0];
                sCp[grp * 49 + col + 1]       = acc[nt][1];
                sCp[(grp + 8) * 49 + col]     = acc[nt][2];
                sCp[(grp + 8) * 49 + col + 1] = acc[nt][3];
            }
        }
        bar_pair(barid);

        const float* sRow = sCp + (u >> 2) * 49 + c0;
#pragma unroll
        for (int q = 0; q < 4; q++) {
            float gr  = sRow[q * 3]     + giv[q * 3]     + bs0[q];
            float gz  = sRow[q * 3 + 1] + giv[q * 3 + 1] + bs1[q];
            float gnh = sRow[q * 3 + 2] + bs3[q];
            float gni = giv[q * 3 + 2] + bs2[q];
            float r = fsig(gr);
            float z = fsig(gz);
            float n = ftanh(gni + r * gnh);
            hreg[q] = (1.f - z) * n + z * hreg[q];
        }
        // packed h store (4 consecutive f16 = 8 B)
        {
            __half2 lo2 = __halves2half2(__float2half_rn(hreg[0]), __float2half_rn(hreg[1]));
            __half2 hi2 = __halves2half2(__float2half_rn(hreg[2]), __float2half_rn(hreg[3]));
            uint2 v;
            v.x = *(const unsigned*)&lo2;
            v.y = *(const unsigned*)&hi2;
            *(uint2*)(g_hf + ((wpar * 2 + dir) * BATCH + brow) * HDIM + jb) = v;
        }

        __syncthreads();
        if (step < S_LEN - 1 && t == 0) {
            __threadfence();
            atomicAdd(&g_bar2[dir], 1u);
        }

        // out store (float4) overlaps barrier wait
        {
            float4 o = make_float4(hreg[0], hreg[1], hreg[2], hreg[3]);
            *(float4*)(out + ((size_t)step * BATCH + brow) * (2 * HDIM) + dir * HDIM + jb) = o;
        }

        if (step < S_LEN - 1) {
            if (t == 0) {
                unsigned target = (unsigned)NBLK_S * (unsigned)(step + 1);
                while (*(volatile unsigned*)&g_bar2[dir] < target) __nanosleep(32);
                __threadfence();
            }
            __syncthreads();
        }
    }
}

// ---------------- launch ----------------
extern "C" void kernel_launch(void* const* d_in, const int* in_sizes, int n_in,
                              void* d_out, int out_size) {
    const float* x     = (const float*)d_in[0];
    const float* Wih_f = (const float*)d_in[1];
    const float* Whh_f = (const float*)d_in[2];
    const float* bih_f = (const float*)d_in[3];
    const float* bhh_f = (const float*)d_in[4];
    const float* Wih_b = (const float*)d_in[5];
    const float* Whh_b = (const float*)d_in[6];
    const float* bih_b = (const float*)d_in[7];
    const float* bhh_b = (const float*)d_in[8];
    float* out = (float*)d_out;

    cudaFuncSetAttribute(gi_gemm,     cudaFuncAttributeMaxDynamicSharedMemorySize, SMEM_G);
    cudaFuncSetAttribute(gru_persist, cudaFuncAttributeMaxDynamicSharedMemorySize, SMEM_P);

    pack_x_kernel<<<(int)((size_t)MTOT * IDIM / 256), 256>>>(x);
    pack_w_kernel<<<2 * N3 * KDIM / 256, 256>>>(Wih_f, Whh_f, Wih_b, Whh_b);
    pack_bias_kernel<<<8, 256>>>(bih_f, bhh_f, bih_b, bhh_b);
    init_h_kernel<<<2 * 2 * BATCH * HDIM / 256, 256>>>();

    gi_gemm<<<dim3(NBLK_G, MTOT / 128, 2), 512, SMEM_G>>>();

    gru_persist<<<dim3(NBLK_S, 2), 512, SMEM_P>>>(out);
}

// round 14
// speedup vs baseline: 2.0716x; 1.1480x over previous
#include <cuda_runtime.h>
#include <cuda_fp16.h>
#include <stdint.h>

typedef __half f16;

#define S_LEN 512
#define BATCH 128
#define IDIM  1024
#define HDIM  1024
#define KDIM  2048       // packed weights: k<1024 -> Wih, k>=1024 -> Whh
#define N3    3072       // 3 gates * H, interleaved col = 3*j + gate
#define MTOT  (S_LEN*BATCH)

#define TN_S  48               // step N tile (one warp covers all 48 cols)
#define TN_G  96               // gi N tile   (2 ngrp x 48)
#define NBLK_S (N3/TN_S)       // 64
#define NBLK_G (N3/TN_G)       // 32

// ---- gi GEMM layout (KT=32/ASTR=40) ----
#define KT    32
#define ASTR  40
#define NSTG  3
#define STAGE_G ((128 + TN_G)*ASTR)        // 8960 f16
#define SMEM_G  (NSTG*STAGE_G*2)           // 53760 B

// ---- persistent kernel layout (KT=64 / ASTR=72, warp-private A) ----
#define KTP    64
#define ASTRP  72
#define NKTP   (HDIM/KTP)                  // 16
#define APAIR  (16*ASTRP)                  // 1152 f16 per warp stage
#define APBLK  (NSTG*APAIR)                // 3456 f16 per warp
#define W_OFF  (8*APBLK)                   // 27648 f16
#define W_CH   (TN_S*ASTRP)                // 3456 f16 per k-chunk
#define BIAS_OFF (W_OFF + NKTP*W_CH)       // 82944 f16
#define SMEM_P (BIAS_OFF*2 + 64*4)         // 165888 + 256 = 166144 B

// ---------------- device scratch ----------------
__device__ f16   g_x[(size_t)MTOT*IDIM];
__device__ f16   g_W[(size_t)2*N3*KDIM];     // [dir][n][k] fp16
__device__ float g_bias[2][4][HDIM];         // br, bz, b_in, b_hn
__device__ f16   g_hf[2*2*BATCH*HDIM];       // [parity][dir][b][j]
__device__ float g_gi[(size_t)2*MTOT*N3];    // precomputed x@Wih^T
__device__ unsigned g_bar2[2];               // per-dir barrier counters

// ---------------- helpers ----------------
__device__ __forceinline__ void cp16(f16* dst, const f16* src) {
    unsigned d = (unsigned)__cvta_generic_to_shared(dst);
    asm volatile("cp.async.cg.shared.global [%0], [%1], 16;\n" :: "r"(d), "l"(src));
}
__device__ __forceinline__ uint32_t smaddr(const void* p) {
    return (uint32_t)__cvta_generic_to_shared(p);
}
__device__ __forceinline__ void ldsm_x4(uint32_t r[4], uint32_t a) {
    asm volatile("ldmatrix.sync.aligned.m8n8.x4.shared.b16 {%0,%1,%2,%3},[%4];"
                 : "=r"(r[0]), "=r"(r[1]), "=r"(r[2]), "=r"(r[3]) : "r"(a));
}
__device__ __forceinline__ void mma16816(float c[4], const uint32_t a[4],
                                         uint32_t b0, uint32_t b1) {
    asm volatile(
        "mma.sync.aligned.m16n8k16.row.col.f32.f16.f16.f32 "
        "{%0,%1,%2,%3},{%4,%5,%6,%7},{%8,%9},{%0,%1,%2,%3};"
        : "+f"(c[0]), "+f"(c[1]), "+f"(c[2]), "+f"(c[3])
        : "r"(a[0]), "r"(a[1]), "r"(a[2]), "r"(a[3]), "r"(b0), "r"(b1));
}
__device__ __forceinline__ float fsig(float x) {
    return __fdividef(1.f, 1.f + __expf(-x));
}
__device__ __forceinline__ float ftanh(float x) {
    return 1.f - __fdividef(2.f, __expf(2.f * x) + 1.f);
}

#define CP_COMMIT() asm volatile("cp.async.commit_group;")

// ---------------- prep kernels ----------------
__global__ void pack_x_kernel(const float* __restrict__ x) {
    int i = blockIdx.x * 256 + threadIdx.x;
    g_x[i] = __float2half_rn(x[i]);
}

__global__ void pack_w_kernel(const float* __restrict__ Wih_f, const float* __restrict__ Whh_f,
                              const float* __restrict__ Wih_b, const float* __restrict__ Whh_b) {
    int idx = blockIdx.x * 256 + threadIdx.x;
    int k   = idx % KDIM;
    int n   = (idx / KDIM) % N3;
    int dir = idx / (KDIM * N3);
    int j = n / 3, g = n % 3;
    int srow = g * HDIM + j;
    const float* Wih = dir ? Wih_b : Wih_f;
    const float* Whh = dir ? Whh_b : Whh_f;
    float v = (k < IDIM) ? Wih[srow * IDIM + k] : Whh[srow * HDIM + (k - IDIM)];
    g_W[idx] = __float2half_rn(v);
}

__global__ void pack_bias_kernel(const float* __restrict__ bih_f, const float* __restrict__ bhh_f,
                                 const float* __restrict__ bih_b, const float* __restrict__ bhh_b) {
    int i = blockIdx.x * 256 + threadIdx.x;   // 0..2047
    int dir = i >> 10, j = i & 1023;
    const float* bih = dir ? bih_b : bih_f;
    const float* bhh = dir ? bhh_b : bhh_f;
    g_bias[dir][0][j] = bih[j] + bhh[j];
    g_bias[dir][1][j] = bih[HDIM + j] + bhh[HDIM + j];
    g_bias[dir][2][j] = bih[2 * HDIM + j];
    g_bias[dir][3][j] = bhh[2 * HDIM + j];
}

__global__ void init_h_kernel() {
    int i = blockIdx.x * 256 + threadIdx.x;   // 2*2*B*H
    g_hf[i] = __float2half_rn(0.f);
    if (i < 2) g_bar2[i] = 0u;
}

// ---------------- warp compute over 32 k ----------------
template<int NT, int AST>
__device__ __forceinline__ void compute_tile(f16* pA, f16* pB, int mwarp, int ngrp,
                                             int lane, float acc[NT][4]) {
    const uint32_t aoff = smaddr(pA + (mwarp * 16 + (lane & 15)) * AST + (lane >> 4) * 8);
    const uint32_t boff = smaddr(pB + (ngrp * (NT * 8) + (lane & 7)) * AST + (lane >> 3) * 8);
    uint32_t a0[4], a1[4];
    ldsm_x4(a0, aoff);
    ldsm_x4(a1, aoff + 16 * 2);
#pragma unroll
    for (int nt = 0; nt < NT; ++nt) {
        uint32_t b4[4];
        ldsm_x4(b4, boff + nt * 8 * AST * 2);
        mma16816(acc[nt], a0, b4[0], b4[1]);
        mma16816(acc[nt], a1, b4[2], b4[3]);
    }
}

// warp-private variant: A buffer holds only this warp's 16 rows; NT=6 covers 48 cols
template<int NT>
__device__ __forceinline__ void compute_warp(f16* pA, f16* pW, int lane, float acc[NT][4]) {
    const uint32_t aoff = smaddr(pA + (lane & 15) * ASTRP + (lane >> 4) * 8);
    const uint32_t boff = smaddr(pW + (lane & 7) * ASTRP + (lane >> 3) * 8);
    uint32_t a0[4], a1[4];
    ldsm_x4(a0, aoff);
    ldsm_x4(a1, aoff + 16 * 2);
#pragma unroll
    for (int nt = 0; nt < NT; ++nt) {
        uint32_t b4[4];
        ldsm_x4(b4, boff + nt * 8 * ASTRP * 2);
        mma16816(acc[nt], a0, b4[0], b4[1]);
        mma16816(acc[nt], a1, b4[2], b4[3]);
    }
}

// ---------------- pre-GEMM: gi = x @ Wih^T (unchanged — at HMMA pipe ceiling) ----------------
// grid: (NBLK_G=32, MTOT/128=512, 2), block 512 (16 warps: 8 M x 2 N)
__global__ void __launch_bounds__(512) gi_gemm() {
    extern __shared__ char smraw[];
    f16* sm = (f16*)smraw;

    const int nblk = blockIdx.x, mblk = blockIdx.y, dir = blockIdx.z;
    const int t = threadIdx.x, warp = t >> 5, lane = t & 31;
    const int mwarp = warp & 7, ngrp = warp >> 3;
    const int grp = lane >> 2, tq = lane & 3;

    auto stage = [&](int s) { return sm + s * STAGE_G; };

    auto copy_tile = [&](int kt, int buf) {
        f16* st = stage(buf);
        const int k0 = kt * KT;
        {
            int row = t >> 2;
            int kq  = (t & 3) * 8;
            size_t off = ((size_t)mblk * 128 + row) * IDIM + k0 + kq;
            cp16(st + row * ASTR + kq, g_x + off);
        }
        if (t < 4 * TN_G) {
            int nloc = t >> 2;
            int kq   = (t & 3) * 8;
            size_t off = ((size_t)(dir * N3 + nblk * TN_G + nloc)) * KDIM + k0 + kq;
            cp16(st + 128 * ASTR + nloc * ASTR + kq, g_W + off);
        }
    };

    float acc[6][4];
#pragma unroll
    for (int i = 0; i < 6; i++)
#pragma unroll
        for (int q = 0; q < 4; q++) acc[i][q] = 0.f;

    copy_tile(0, 0); CP_COMMIT();
    copy_tile(1, 1); CP_COMMIT();

    const int NKT = IDIM / KT;   // 32
#pragma unroll 1
    for (int kt = 0; kt < NKT; ++kt) {
        if (kt < NKT - 1) asm volatile("cp.async.wait_group 1;");
        else              asm volatile("cp.async.wait_group 0;");
        __syncthreads();
        if (kt + 2 < NKT) { copy_tile(kt + 2, (kt + 2) % NSTG); CP_COMMIT(); }
        compute_tile<6, ASTR>(stage(kt % NSTG), stage(kt % NSTG) + 128 * ASTR,
                              mwarp, ngrp, lane, acc);
    }

    const int m = mblk * 128 + mwarp * 16 + grp;
    const int colbase = nblk * TN_G + ngrp * 48 + tq * 2;
    float* d0 = g_gi + ((size_t)dir * MTOT + m) * N3;
    float* d1 = d0 + (size_t)8 * N3;
#pragma unroll
    for (int nt = 0; nt < 6; ++nt) {
        int col = colbase + nt * 8;
        d0[col]     = acc[nt][0];
        d0[col + 1] = acc[nt][1];
        d1[col]     = acc[nt][2];
        d1[col + 1] = acc[nt][3];
    }
}

// ---------------- persistent recurrent kernel ----------------
// grid: (NBLK_S=64, 2) = 128 CTAs, block 256 (8 independent warps).
// Warp w owns rows [16w,16w+16) x all 48 cols: fully warp-synchronous mainloop
// (cp.async wait + __syncwarp only), zero intra-step block barriers.
__global__ void __launch_bounds__(256) gru_persist(float* __restrict__ out) {
    extern __shared__ char smraw[];
    f16* sm  = (f16*)smraw;
    f16* wsm = sm + W_OFF;
    float* sbias = (float*)(smraw + BIAS_OFF * 2);   // [4][16]

    const int nblk = blockIdx.x, dir = blockIdx.y;
    const int t = threadIdx.x, w = t >> 5, lane = t & 31;
    const int grp = lane >> 2, tq = lane & 3;
    f16* awarp = sm + w * APBLK;

    // ---- preload Whh tile: 16 chunks x 48 rows x 64 k ----
    for (int i = t; i < NKTP * TN_S * 8; i += 256) {
        int kt   = i / (TN_S * 8);
        int r    = i % (TN_S * 8);
        int nloc = r >> 3, kq = (r & 7) * 8;
        size_t off = ((size_t)(dir * N3 + nblk * TN_S + nloc)) * KDIM + IDIM + kt * KTP + kq;
        cp16(wsm + kt * W_CH + nloc * ASTRP + kq, g_W + off);
    }
    if (t < 64) sbias[t] = g_bias[dir][t >> 4][nblk * 16 + (t & 15)];
    CP_COMMIT();
    asm volatile("cp.async.wait_group 0;");
    __syncthreads();

    // ---- per-thread persistent state: one b, 8 consecutive j ----
    const int brl    = lane >> 1;                    // row within warp block (0..15)
    const int jh     = lane & 1;                     // j-half (0/1): 8 j's each
    const int brow_g = w * 16 + brl;                 // global batch row
    const int jb     = nblk * 16 + jh * 8;           // first of 8 consecutive j
    float hreg[8];
#pragma unroll
    for (int q = 0; q < 8; q++) hreg[q] = 0.f;

#pragma unroll 1
    for (int step = 0; step < S_LEN; ++step) {
        const int rpar = step & 1, wpar = rpar ^ 1;
        const int s_x  = dir ? (S_LEN - 1 - step) : step;
        const int hbase = (rpar * 2 + dir) * BATCH * HDIM;

        auto copyA = [&](int kt, int buf) {
            f16* st = awarp + buf * APAIR;
#pragma unroll
            for (int i = 0; i < 4; i++) {
                int slot = lane + 32 * i;            // 128 slots: 16 rows x 8 kq
                int rl = slot >> 3, kq = (slot & 7) * 8;
                int off = hbase + (w * 16 + rl) * HDIM + kt * KTP + kq;
                cp16(st + rl * ASTRP + kq, g_hf + off);
            }
        };

        float acc[6][4];
#pragma unroll
        for (int i = 0; i < 6; i++)
#pragma unroll
            for (int q = 0; q < 4; q++) acc[i][q] = 0.f;

        copyA(0, 0); CP_COMMIT();
        copyA(1, 1); CP_COMMIT();

        // ---- prefetch gi: 24 consecutive floats (row brow_g, cols jh*24..) ----
        const float* gp = g_gi + ((size_t)dir * MTOT + (size_t)s_x * BATCH + brow_g) * N3
                          + nblk * TN_S + jh * 24;
        float giv[24];
#pragma unroll
        for (int i = 0; i < 6; i++) {
            float4 v = __ldg((const float4*)(gp + i * 4));
            giv[i * 4] = v.x; giv[i * 4 + 1] = v.y; giv[i * 4 + 2] = v.z; giv[i * 4 + 3] = v.w;
        }

#pragma unroll 1
        for (int kt = 0; kt < NKTP; ++kt) {
            if (kt < NKTP - 1) asm volatile("cp.async.wait_group 1;");
            else               asm volatile("cp.async.wait_group 0;");
            __syncwarp();
            if (kt + 2 < NKTP) { copyA(kt + 2, (kt + 2) % NSTG); CP_COMMIT(); }
            f16* pA = awarp + (kt % NSTG) * APAIR;
            f16* pW = wsm + kt * W_CH;
            compute_warp<6>(pA, pW, lane, acc);
            compute_warp<6>(pA + 32, pW + 32, lane, acc);
        }

        // ---- warp-local epilogue: frags -> warp scratch (A stages) -> gates ----
        float* sC = (float*)awarp;                    // 16 x 49 floats = 3136 B < APBLK*2
        {
#pragma unroll
            for (int nt = 0; nt < 6; ++nt) {
                int col = nt * 8 + tq * 2;
                sC[grp * 49 + col]           = acc[nt][0];
                sC[grp * 49 + col + 1]       = acc[nt][1];
                sC[(grp + 8) * 49 + col]     = acc[nt][2];
                sC[(grp + 8) * 49 + col + 1] = acc[nt][3];
            }
        }
        __syncwarp();

        const float* sRow = sC + brl * 49 + jh * 24;
#pragma unroll
        for (int q = 0; q < 8; q++) {
            int jl = jh * 8 + q;
            float gr  = sRow[q * 3]     + giv[q * 3]     + sbias[jl];
            float gz  = sRow[q * 3 + 1] + giv[q * 3 + 1] + sbias[16 + jl];
            float gnh = sRow[q * 3 + 2] + sbias[48 + jl];
            float gni = giv[q * 3 + 2] + sbias[32 + jl];
            float r = fsig(gr);
            float z = fsig(gz);
            float n = ftanh(gni + r * gnh);
            hreg[q] = (1.f - z) * n + z * hreg[q];
        }
        __syncwarp();                                  // sC reads done before next-step copyA

        // packed h store (8 consecutive f16 = 16 B)
        {
            __half2 p0 = __halves2half2(__float2half_rn(hreg[0]), __float2half_rn(hreg[1]));
            __half2 p1 = __halves2half2(__float2half_rn(hreg[2]), __float2half_rn(hreg[3]));
            __half2 p2 = __halves2half2(__float2half_rn(hreg[4]), __float2half_rn(hreg[5]));
            __half2 p3 = __halves2half2(__float2half_rn(hreg[6]), __float2half_rn(hreg[7]));
            uint4 v;
            v.x = *(const unsigned*)&p0;
            v.y = *(const unsigned*)&p1;
            v.z = *(const unsigned*)&p2;
            v.w = *(const unsigned*)&p3;
            *(uint4*)(g_hf + ((wpar * 2 + dir) * BATCH + brow_g) * HDIM + jb) = v;
        }

        __syncthreads();
        if (step < S_LEN - 1 && t == 0) {
            __threadfence();
            atomicAdd(&g_bar2[dir], 1u);
        }

        // out store (2x float4) overlaps barrier wait
        {
            float* op = out + ((size_t)step * BATCH + brow_g) * (2 * HDIM) + dir * HDIM + jb;
            *(float4*)op       = make_float4(hreg[0], hreg[1], hreg[2], hreg[3]);
            *(float4*)(op + 4) = make_float4(hreg[4], hreg[5], hreg[6], hreg[7]);
        }

        if (step < S_LEN - 1) {
            if (t == 0) {
                unsigned target = (unsigned)NBLK_S * (unsigned)(step + 1);
                while (*(volatile unsigned*)&g_bar2[dir] < target) __nanosleep(32);
                __threadfence();
            }
            __syncthreads();
        }
    }
}

// ---------------- launch ----------------
extern "C" void kernel_launch(void* const* d_in, const int* in_sizes, int n_in,
                              void* d_out, int out_size) {
    const float* x     = (const float*)d_in[0];
    const float* Wih_f = (const float*)d_in[1];
    const float* Whh_f = (const float*)d_in[2];
    const float* bih_f = (const float*)d_in[3];
    const float* bhh_f = (const float*)d_in[4];
    const float* Wih_b = (const float*)d_in[5];
    const float* Whh_b = (const float*)d_in[6];
    const float* bih_b = (const float*)d_in[7];
    const float* bhh_b = (const float*)d_in[8];
    float* out = (float*)d_out;

    cudaFuncSetAttribute(gi_gemm,     cudaFuncAttributeMaxDynamicSharedMemorySize, SMEM_G);
    cudaFuncSetAttribute(gru_persist, cudaFuncAttributeMaxDynamicSharedMemorySize, SMEM_P);

    pack_x_kernel<<<(int)((size_t)MTOT * IDIM / 256), 256>>>(x);
    pack_w_kernel<<<2 * N3 * KDIM / 256, 256>>>(Wih_f, Whh_f, Wih_b, Whh_b);
    pack_bias_kernel<<<8, 256>>>(bih_f, bhh_f, bih_b, bhh_b);
    init_h_kernel<<<2 * 2 * BATCH * HDIM / 256, 256>>>();

    gi_gemm<<<dim3(NBLK_G, MTOT / 128, 2), 512, SMEM_G>>>();

    gru_persist<<<dim3(NBLK_S, 2), 256, SMEM_P>>>(out);
}

// round 15
// speedup vs baseline: 2.1121x; 1.0195x over previous
#include <cuda_runtime.h>
#include <cuda_fp16.h>
#include <stdint.h>

typedef __half f16;

#define S_LEN 512
#define BATCH 128
#define IDIM  1024
#define HDIM  1024
#define KDIM  2048       // packed Whh at k offset IDIM in g_W
#define N3    3072       // 3 gates * H, interleaved col = 3*j + gate
#define MTOT  (S_LEN*BATCH)

#define TN_S  48               // per-CTA N tile
#define NBLK_S (N3/TN_S)       // 64

// ---- persistent kernel layout (KT=64 / ASTR=72, warp-private A) ----
#define NSTG   3
#define KTP    64
#define ASTRP  72
#define NKTP   (HDIM/KTP)                  // 16
#define APAIR  (16*ASTRP)                  // 1152 f16 per warp stage
#define APBLK  (NSTG*APAIR)                // 3456 f16 per warp
#define W_OFF  (8*APBLK)                   // 27648 f16
#define W_CH   (TN_S*ASTRP)                // 3456 f16 per k-chunk
#define BIAS_OFF (W_OFF + NKTP*W_CH)       // 82944 f16
#define SCGI_OFF (BIAS_OFF*2 + 256)        // bytes: after 64-float bias table
#define SC_PAIR  (16*49)                   // 784 floats per warp
#define SMEM_P   (SCGI_OFF + 8*SC_PAIR*4)  // 165888+256+25088 = 191232 B

// ---------------- device scratch ----------------
__device__ f16   g_x[(size_t)MTOT*IDIM];
__device__ f16   g_W[(size_t)2*N3*KDIM];      // Whh at [dir][n][IDIM + k]
__device__ uint4 g_wfrag[(size_t)2*NBLK_S*6144];   // Wih in MMA-fragment order
__device__ float g_bias[2][4][HDIM];          // br, bz, b_in, b_hn
__device__ f16   g_hf[2*2*BATCH*HDIM];        // [parity][dir][b][j]
__device__ unsigned g_bar2[2];                // per-dir barrier counters

// ---------------- helpers ----------------
__device__ __forceinline__ void cp16(f16* dst, const f16* src) {
    unsigned d = (unsigned)__cvta_generic_to_shared(dst);
    asm volatile("cp.async.cg.shared.global [%0], [%1], 16;\n" :: "r"(d), "l"(src));
}
__device__ __forceinline__ uint32_t smaddr(const void* p) {
    return (uint32_t)__cvta_generic_to_shared(p);
}
__device__ __forceinline__ void ldsm_x4(uint32_t r[4], uint32_t a) {
    asm volatile("ldmatrix.sync.aligned.m8n8.x4.shared.b16 {%0,%1,%2,%3},[%4];"
                 : "=r"(r[0]), "=r"(r[1]), "=r"(r[2]), "=r"(r[3]) : "r"(a));
}
__device__ __forceinline__ void mma16816(float c[4], const uint32_t a[4],
                                         uint32_t b0, uint32_t b1) {
    asm volatile(
        "mma.sync.aligned.m16n8k16.row.col.f32.f16.f16.f32 "
        "{%0,%1,%2,%3},{%4,%5,%6,%7},{%8,%9},{%0,%1,%2,%3};"
        : "+f"(c[0]), "+f"(c[1]), "+f"(c[2]), "+f"(c[3])
        : "r"(a[0]), "r"(a[1]), "r"(a[2]), "r"(a[3]), "r"(b0), "r"(b1));
}
__device__ __forceinline__ float fsig(float x) {
    return __fdividef(1.f, 1.f + __expf(-x));
}
__device__ __forceinline__ float ftanh(float x) {
    return 1.f - __fdividef(2.f, __expf(2.f * x) + 1.f);
}

#define CP_COMMIT() asm volatile("cp.async.commit_group;")

// ---------------- prep kernels ----------------
__global__ void pack_x_kernel(const float* __restrict__ x) {
    int i = blockIdx.x * 256 + threadIdx.x;
    g_x[i] = __float2half_rn(x[i]);
}

// Whh -> g_W (gate-interleaved rows, k at offset IDIM)
__global__ void pack_whh_kernel(const float* __restrict__ Whh_f, const float* __restrict__ Whh_b) {
    int idx = blockIdx.x * 256 + threadIdx.x;   // over 2*N3*HDIM
    int k   = idx & 1023;
    int n   = (idx >> 10) % N3;
    int dir = idx / (N3 * 1024);
    int j = n / 3, g = n % 3;
    const float* W = dir ? Whh_b : Whh_f;
    g_W[((size_t)dir * N3 + n) * KDIM + IDIM + k] =
        __float2half_rn(W[(g * HDIM + j) * HDIM + k]);
}

// Wih -> MMA-fragment layout: uint4 per (dir,nblk,kt,g2,lane), word i = b4[i]
__global__ void pack_wfrag_kernel(const float* __restrict__ Wih_f, const float* __restrict__ Wih_b) {
    int idx = blockIdx.x * 256 + threadIdx.x;   // over 2*64*16*12*32*4 = 3145728 u32
    int word = idx & 3;
    int lane = (idx >> 2) & 31;
    int v    = idx >> 7;
    int g2   = v % 12;
    int kt   = (v / 12) % 16;
    int nblk = (v / 192) % 64;
    int dir  = v / 12288;
    int nt = g2 >> 1, call = g2 & 1;
    int n = nblk * 48 + nt * 8 + (lane >> 2);
    int k = kt * 64 + call * 32 + word * 8 + (lane & 3) * 2;
    int srow = (n % 3) * HDIM + n / 3;
    const float* W = dir ? Wih_b : Wih_f;
    __half2 h2 = __halves2half2(__float2half_rn(W[(size_t)srow * IDIM + k]),
                                __float2half_rn(W[(size_t)srow * IDIM + k + 1]));
    ((uint32_t*)g_wfrag)[idx] = *(uint32_t*)&h2;
}

__global__ void pack_bias_kernel(const float* __restrict__ bih_f, const float* __restrict__ bhh_f,
                                 const float* __restrict__ bih_b, const float* __restrict__ bhh_b) {
    int i = blockIdx.x * 256 + threadIdx.x;   // 0..2047
    int dir = i >> 10, j = i & 1023;
    const float* bih = dir ? bih_b : bih_f;
    const float* bhh = dir ? bhh_b : bhh_f;
    g_bias[dir][0][j] = bih[j] + bhh[j];
    g_bias[dir][1][j] = bih[HDIM + j] + bhh[HDIM + j];
    g_bias[dir][2][j] = bih[2 * HDIM + j];
    g_bias[dir][3][j] = bhh[2 * HDIM + j];
}

__global__ void init_h_kernel() {
    int i = blockIdx.x * 256 + threadIdx.x;   // 2*2*B*H
    g_hf[i] = __float2half_rn(0.f);
    if (i < 2) g_bar2[i] = 0u;
}

// warp-private gh compute: A = this warp's 16 rows; NT=6 covers 48 cols; 32 k
template<int NT>
__device__ __forceinline__ void compute_warp(f16* pA, f16* pW, int lane, float acc[NT][4]) {
    const uint32_t aoff = smaddr(pA + (lane & 15) * ASTRP + (lane >> 4) * 8);
    const uint32_t boff = smaddr(pW + (lane & 7) * ASTRP + (lane >> 3) * 8);
    uint32_t a0[4], a1[4];
    ldsm_x4(a0, aoff);
    ldsm_x4(a1, aoff + 16 * 2);
#pragma unroll
    for (int nt = 0; nt < NT; ++nt) {
        uint32_t b4[4];
        ldsm_x4(b4, boff + nt * 8 * ASTRP * 2);
        mma16816(acc[nt], a0, b4[0], b4[1]);
        mma16816(acc[nt], a1, b4[2], b4[3]);
    }
}

// ---------------- persistent fused kernel ----------------
// grid: (NBLK_S=64, 2) = 128 CTAs, block 256 (8 independent warps).
// Per step: gh mainloop (Whh resident) -> epilogue (consumes smem gi from prev
// step) -> h publish + barrier arrive -> gi phase for step+1 (x via cp.async,
// Wih via fragment-layout LDG.128 from L2) overlapping the barrier wait.
__global__ void __launch_bounds__(256) gru_persist(float* __restrict__ out) {
    extern __shared__ char smraw[];
    f16* sm  = (f16*)smraw;
    f16* wsm = sm + W_OFF;
    float* sbias = (float*)(smraw + BIAS_OFF * 2);   // [4][16]

    const int nblk = blockIdx.x, dir = blockIdx.y;
    const int t = threadIdx.x, w = t >> 5, lane = t & 31;
    const int grp = lane >> 2, tq = lane & 3;
    f16* awarp = sm + w * APBLK;
    float* sGi = (float*)(smraw + SCGI_OFF) + w * SC_PAIR;   // 16 x 49 floats

    // ---- preload Whh tile: 16 chunks x 48 rows x 64 k ----
    for (int i = t; i < NKTP * TN_S * 8; i += 256) {
        int kt   = i / (TN_S * 8);
        int r    = i % (TN_S * 8);
        int nloc = r >> 3, kq = (r & 7) * 8;
        size_t off = ((size_t)(dir * N3 + nblk * TN_S + nloc)) * KDIM + IDIM + kt * KTP + kq;
        cp16(wsm + kt * W_CH + nloc * ASTRP + kq, g_W + off);
    }
    if (t < 64) sbias[t] = g_bias[dir][t >> 4][nblk * 16 + (t & 15)];
    CP_COMMIT();
    asm volatile("cp.async.wait_group 0;");
    __syncthreads();

    // ---- per-thread persistent state: one b, 8 consecutive j ----
    const int brl    = lane >> 1;                    // row within warp block (0..15)
    const int jh     = lane & 1;                     // j-half (0/1): 8 j's each
    const int brow_g = w * 16 + brl;                 // global batch row
    const int jb     = nblk * 16 + jh * 8;           // first of 8 consecutive j
    float hreg[8];
#pragma unroll
    for (int q = 0; q < 8; q++) hreg[q] = 0.f;

    const uint4* wfp = g_wfrag + (size_t)(dir * NBLK_S + nblk) * 6144 + lane;

    // ---- gi phase: compute x[tf] @ Wih tile -> sGi (warp-local, no barriers) ----
    auto gi_phase = [&](int tf) {
        auto copyX = [&](int kt, int buf) {
            f16* st = awarp + buf * APAIR;
#pragma unroll
            for (int i = 0; i < 4; i++) {
                int slot = lane + 32 * i;
                int rl = slot >> 3, kq = (slot & 7) * 8;
                size_t off = ((size_t)tf * BATCH + w * 16 + rl) * IDIM + kt * KTP + kq;
                cp16(st + rl * ASTRP + kq, g_x + off);
            }
        };
        float acci[6][4];
#pragma unroll
        for (int i = 0; i < 6; i++)
#pragma unroll
            for (int q = 0; q < 4; q++) acci[i][q] = 0.f;

        copyX(0, 0); CP_COMMIT();
        copyX(1, 1); CP_COMMIT();

#pragma unroll 1
        for (int kt = 0; kt < NKTP; ++kt) {
            uint4 bf[12];
#pragma unroll
            for (int g2 = 0; g2 < 12; g2++) bf[g2] = __ldg(wfp + (kt * 12 + g2) * 32);
            if (kt < NKTP - 1) asm volatile("cp.async.wait_group 1;");
            else               asm volatile("cp.async.wait_group 0;");
            __syncwarp();
            if (kt + 2 < NKTP) { copyX(kt + 2, (kt + 2) % NSTG); CP_COMMIT(); }
            f16* pA = awarp + (kt % NSTG) * APAIR;
            const uint32_t ab = smaddr(pA + (lane & 15) * ASTRP + (lane >> 4) * 8);
            uint32_t a0[4], a1[4], a2[4], a3[4];
            ldsm_x4(a0, ab);            // k 0..16
            ldsm_x4(a1, ab + 32);       // k 16..32
            ldsm_x4(a2, ab + 64);       // k 32..48
            ldsm_x4(a3, ab + 96);       // k 48..64
#pragma unroll
            for (int nt = 0; nt < 6; ++nt) {
                mma16816(acci[nt], a0, bf[nt * 2].x,     bf[nt * 2].y);
                mma16816(acci[nt], a1, bf[nt * 2].z,     bf[nt * 2].w);
                mma16816(acci[nt], a2, bf[nt * 2 + 1].x, bf[nt * 2 + 1].y);
                mma16816(acci[nt], a3, bf[nt * 2 + 1].z, bf[nt * 2 + 1].w);
            }
        }
        __syncwarp();
#pragma unroll
        for (int nt = 0; nt < 6; ++nt) {
            int col = nt * 8 + tq * 2;
            sGi[grp * 49 + col]           = acci[nt][0];
            sGi[grp * 49 + col + 1]       = acci[nt][1];
            sGi[(grp + 8) * 49 + col]     = acci[nt][2];
            sGi[(grp + 8) * 49 + col + 1] = acci[nt][3];
        }
        __syncwarp();
    };

    // prologue: gi for step 0
    gi_phase(dir ? (S_LEN - 1) : 0);

#pragma unroll 1
    for (int step = 0; step < S_LEN; ++step) {
        const int rpar = step & 1, wpar = rpar ^ 1;
        const int hbase = (rpar * 2 + dir) * BATCH * HDIM;

        auto copyA = [&](int kt, int buf) {
            f16* st = awarp + buf * APAIR;
#pragma unroll
            for (int i = 0; i < 4; i++) {
                int slot = lane + 32 * i;            // 128 slots: 16 rows x 8 kq
                int rl = slot >> 3, kq = (slot & 7) * 8;
                int off = hbase + (w * 16 + rl) * HDIM + kt * KTP + kq;
                cp16(st + rl * ASTRP + kq, g_hf + off);
            }
        };

        float acc[6][4];
#pragma unroll
        for (int i = 0; i < 6; i++)
#pragma unroll
            for (int q = 0; q < 4; q++) acc[i][q] = 0.f;

        copyA(0, 0); CP_COMMIT();
        copyA(1, 1); CP_COMMIT();

#pragma unroll 1
        for (int kt = 0; kt < NKTP; ++kt) {
            if (kt < NKTP - 1) asm volatile("cp.async.wait_group 1;");
            else               asm volatile("cp.async.wait_group 0;");
            __syncwarp();
            if (kt + 2 < NKTP) { copyA(kt + 2, (kt + 2) % NSTG); CP_COMMIT(); }
            f16* pA = awarp + (kt % NSTG) * APAIR;
            f16* pW = wsm + kt * W_CH;
            compute_warp<6>(pA, pW, lane, acc);
            compute_warp<6>(pA + 32, pW + 32, lane, acc);
        }

        // ---- warp-local epilogue: frags -> warp scratch -> gates (gi from sGi) ----
        float* sC = (float*)awarp;                    // 16 x 49 floats
        {
#pragma unroll
            for (int nt = 0; nt < 6; ++nt) {
                int col = nt * 8 + tq * 2;
                sC[grp * 49 + col]           = acc[nt][0];
                sC[grp * 49 + col + 1]       = acc[nt][1];
                sC[(grp + 8) * 49 + col]     = acc[nt][2];
                sC[(grp + 8) * 49 + col + 1] = acc[nt][3];
            }
        }
        __syncwarp();

        const float* sRow = sC + brl * 49 + jh * 24;
        const float* sRowGi = sGi + brl * 49 + jh * 24;
#pragma unroll
        for (int q = 0; q < 8; q++) {
            int jl = jh * 8 + q;
            float gr  = sRow[q * 3]     + sRowGi[q * 3]     + sbias[jl];
            float gz  = sRow[q * 3 + 1] + sRowGi[q * 3 + 1] + sbias[16 + jl];
            float gnh = sRow[q * 3 + 2] + sbias[48 + jl];
            float gni = sRowGi[q * 3 + 2] + sbias[32 + jl];
            float r = fsig(gr);
            float z = fsig(gz);
            float n = ftanh(gni + r * gnh);
            hreg[q] = (1.f - z) * n + z * hreg[q];
        }
        __syncwarp();                                  // sC/sGi reads done

        // packed h store (8 consecutive f16 = 16 B)
        {
            __half2 p0 = __halves2half2(__float2half_rn(hreg[0]), __float2half_rn(hreg[1]));
            __half2 p1 = __halves2half2(__float2half_rn(hreg[2]), __float2half_rn(hreg[3]));
            __half2 p2 = __halves2half2(__float2half_rn(hreg[4]), __float2half_rn(hreg[5]));
            __half2 p3 = __halves2half2(__float2half_rn(hreg[6]), __float2half_rn(hreg[7]));
            uint4 v;
            v.x = *(const unsigned*)&p0;
            v.y = *(const unsigned*)&p1;
            v.z = *(const unsigned*)&p2;
            v.w = *(const unsigned*)&p3;
            *(uint4*)(g_hf + ((wpar * 2 + dir) * BATCH + brow_g) * HDIM + jb) = v;
        }

        __syncthreads();
        if (step < S_LEN - 1 && t == 0) {
            __threadfence();
            atomicAdd(&g_bar2[dir], 1u);
        }

        // out store (2x float4)
        {
            float* op = out + ((size_t)step * BATCH + brow_g) * (2 * HDIM) + dir * HDIM + jb;
            *(float4*)op       = make_float4(hreg[0], hreg[1], hreg[2], hreg[3]);
            *(float4*)(op + 4) = make_float4(hreg[4], hreg[5], hreg[6], hreg[7]);
        }

        if (step < S_LEN - 1) {
            // gi for the NEXT step — overlaps the barrier wait (independent of h)
            const int s2 = step + 1;
            gi_phase(dir ? (S_LEN - 1 - s2) : s2);

            if (t == 0) {
                unsigned target = (unsigned)NBLK_S * (unsigned)(step + 1);
                while (*(volatile unsigned*)&g_bar2[dir] < target) __nanosleep(32);
                __threadfence();
            }
            __syncthreads();
        }
    }
}

// ---------------- launch ----------------
extern "C" void kernel_launch(void* const* d_in, const int* in_sizes, int n_in,
                              void* d_out, int out_size) {
    const float* x     = (const float*)d_in[0];
    const float* Wih_f = (const float*)d_in[1];
    const float* Whh_f = (const float*)d_in[2];
    const float* bih_f = (const float*)d_in[3];
    const float* bhh_f = (const float*)d_in[4];
    const float* Wih_b = (const float*)d_in[5];
    const float* Whh_b = (const float*)d_in[6];
    const float* bih_b = (const float*)d_in[7];
    const float* bhh_b = (const float*)d_in[8];
    float* out = (float*)d_out;

    cudaFuncSetAttribute(gru_persist, cudaFuncAttributeMaxDynamicSharedMemorySize, SMEM_P);

    pack_x_kernel<<<(int)((size_t)MTOT * IDIM / 256), 256>>>(x);
    pack_whh_kernel<<<2 * N3 * HDIM / 256, 256>>>(Whh_f, Whh_b);
    pack_wfrag_kernel<<<2 * NBLK_S * 6144 * 4 / 256, 256>>>(Wih_f, Wih_b);
    pack_bias_kernel<<<8, 256>>>(bih_f, bhh_f, bih_b, bhh_b);
    init_h_kernel<<<2 * 2 * BATCH * HDIM / 256, 256>>>();

    gru_persist<<<dim3(NBLK_S, 2), 256, SMEM_P>>>(out);
}